// round 7
// baseline (speedup 1.0000x reference)
#include <cuda_runtime.h>
#include <stdint.h>
#include <math.h>

#define B_  2
#define S_  2048
#define D_  1024
#define H_  16
#define HD_ 64
#define MTOT (B_ * S_)           // 4096

// ---------------------------------------------------------------------------
// Scratch (__device__ globals: allocation-free rule)
// ---------------------------------------------------------------------------
__device__ float g_qkv[(size_t)B_ * S_ * 3 * D_];   // [B,S,3D] (tf32-rounded)
__device__ float g_ctx[(size_t)B_ * S_ * D_];       // [B,S,D]  (tf32-rounded)
__device__ float g_xt[(size_t)MTOT * D_];           // x, tf32-rounded
__device__ float g_wqkv_t[(size_t)3 * D_ * D_];     // W_qkv^T [3D, D]
__device__ float g_wout_t[(size_t)D_ * D_];         // W_out^T [D, D]

// ---------------------------------------------------------------------------
// Helpers (baseline-PTX only: cp.async, ldmatrix, mma.sync)
// ---------------------------------------------------------------------------
__device__ __forceinline__ uint32_t smem_u32(const void* p) {
    uint32_t a;
    asm("{ .reg .u64 t; cvta.to.shared.u64 t, %1; cvt.u32.u64 %0, t; }"
        : "=r"(a) : "l"(p));
    return a;
}
__device__ __forceinline__ float rnd_tf32(float x) {
    uint32_t u;
    asm("cvt.rna.tf32.f32 %0, %1;" : "=r"(u) : "f"(x));
    return __uint_as_float(u);
}
__device__ __forceinline__ void cp16(uint32_t dst, const void* src) {
    asm volatile("cp.async.cg.shared.global [%0], [%1], 16;"
                 :: "r"(dst), "l"(src));
}
__device__ __forceinline__ void cp_commit() {
    asm volatile("cp.async.commit_group;");
}
__device__ __forceinline__ void ldsm_x4(uint32_t addr, uint32_t* r) {
    asm volatile("ldmatrix.sync.aligned.m8n8.x4.shared.b16 {%0,%1,%2,%3}, [%4];"
                 : "=r"(r[0]), "=r"(r[1]), "=r"(r[2]), "=r"(r[3]) : "r"(addr));
}
__device__ __forceinline__ void ldsm_x2(uint32_t addr, uint32_t* r) {
    asm volatile("ldmatrix.sync.aligned.m8n8.x2.shared.b16 {%0,%1}, [%2];"
                 : "=r"(r[0]), "=r"(r[1]) : "r"(addr));
}
__device__ __forceinline__ void mma_tf32(float* c, const uint32_t* a,
                                         uint32_t b0, uint32_t b1) {
    asm volatile(
        "mma.sync.aligned.m16n8k8.row.col.f32.tf32.tf32.f32 "
        "{%0,%1,%2,%3}, {%4,%5,%6,%7}, {%8,%9}, {%0,%1,%2,%3};"
        : "+f"(c[0]), "+f"(c[1]), "+f"(c[2]), "+f"(c[3])
        : "r"(a[0]), "r"(a[1]), "r"(a[2]), "r"(a[3]), "r"(b0), "r"(b1));
}

// GEMM tile addressing: 128B rows (32 floats)
__device__ __forceinline__ uint32_t tile_addr(uint32_t base, int row, int bc) {
    return base + (uint32_t)(row * 128) + (uint32_t)(bc ^ ((row & 7) << 4));
}
// Attention tile addressing: 256B rows (64 floats), 2-level XOR swizzle
__device__ __forceinline__ uint32_t swzA(int row, int bc) {
    int nib = ((row & 7) ^ ((row >> 3) & 7)) << 4;
    return (uint32_t)(row * 256 + (bc ^ nib));
}

// ---------------------------------------------------------------------------
// Pre-pass kernels
// ---------------------------------------------------------------------------
__global__ void round_tf32_vec4(const float* __restrict__ in,
                                float* __restrict__ out, int n4) {
    int i = blockIdx.x * blockDim.x + threadIdx.x;
    if (i < n4) {
        float4 v = ((const float4*)in)[i];
        v.x = rnd_tf32(v.x); v.y = rnd_tf32(v.y);
        v.z = rnd_tf32(v.z); v.w = rnd_tf32(v.w);
        ((float4*)out)[i] = v;
    }
}

__global__ void transpose_round(const float* __restrict__ W,
                                float* __restrict__ Wt, int K, int N) {
    __shared__ float t[32][33];
    int bx = blockIdx.x * 32;
    int by = blockIdx.y * 32;
    int x = threadIdx.x, y = threadIdx.y;   // block (32, 8)
#pragma unroll
    for (int j = 0; j < 32; j += 8)
        t[y + j][x] = W[(size_t)(by + y + j) * N + bx + x];
    __syncthreads();
#pragma unroll
    for (int j = 0; j < 32; j += 8)
        Wt[(size_t)(bx + y + j) * K + by + x] = rnd_tf32(t[x][y + j]);
}

// ---------------------------------------------------------------------------
// Tensor-core tf32 GEMM + bias (mma.sync).
// 3-stage cp.async pipeline, one __syncthreads per K-iter.
// ---------------------------------------------------------------------------
#define GK    1024
#define BK    32
#define NKIT  (GK / BK)
#define STAGE_BYTES 32768
#define NSTAGE 3
#define GSMEM_BYTES (NSTAGE * STAGE_BYTES)

__global__ __launch_bounds__(256, 2)
void gemm_tc(const float* __restrict__ A, const float* __restrict__ Bt,
             const float* __restrict__ bias, float* __restrict__ C, int N,
             int do_round) {
    extern __shared__ char smem[];
    uint32_t sbase = smem_u32(smem);

    int tid  = threadIdx.x;
    int wid  = tid >> 5;
    int lane = tid & 31;
    int wm   = wid >> 2;
    int wn   = wid & 3;
    int brow = blockIdx.y * 128;
    int bcol = blockIdx.x * 128;

    uint32_t aB[NSTAGE], bB[NSTAGE];
#pragma unroll
    for (int s = 0; s < NSTAGE; s++) {
        aB[s] = sbase + s * STAGE_BYTES;
        bB[s] = aB[s] + 16384;
    }

    const float* Agp = A  + (size_t)brow * GK;
    const float* Bgp = Bt + (size_t)bcol * GK;

    int cr = tid >> 3, cc16 = (tid & 7) * 16;

    int a_row_l = ((lane >> 3) & 1) * 8 + (lane & 7);
    int a_bc_l  = (lane >> 4) * 16;
    int b_row_l = lane & 7;
    int b_bc_l  = ((lane >> 3) & 1) * 16;

    float acc[4][4][4];
#pragma unroll
    for (int i = 0; i < 4; i++)
#pragma unroll
        for (int j = 0; j < 4; j++)
#pragma unroll
            for (int k = 0; k < 4; k++) acc[i][j][k] = 0.f;

#pragma unroll
    for (int s = 0; s < 2; s++) {
        int k0 = s * BK;
#pragma unroll
        for (int j = 0; j < 4; j++) {
            int row = cr + j * 32;
            uint32_t off = tile_addr(0, row, cc16);
            cp16(aB[s] + off, Agp + (size_t)row * GK + k0 + (cc16 >> 2));
            cp16(bB[s] + off, Bgp + (size_t)row * GK + k0 + (cc16 >> 2));
        }
        cp_commit();
    }

    for (int it = 0; it < NKIT; it++) {
        if (it + 1 < NKIT) {
            asm volatile("cp.async.wait_group 1;");
        } else {
            asm volatile("cp.async.wait_group 0;");
        }
        __syncthreads();

        if (it + 2 < NKIT) {
            int s  = (it + 2) % NSTAGE;
            int k0 = (it + 2) * BK;
#pragma unroll
            for (int j = 0; j < 4; j++) {
                int row = cr + j * 32;
                uint32_t off = tile_addr(0, row, cc16);
                cp16(aB[s] + off, Agp + (size_t)row * GK + k0 + (cc16 >> 2));
                cp16(bB[s] + off, Bgp + (size_t)row * GK + k0 + (cc16 >> 2));
            }
            cp_commit();
        }

        int buf = it % NSTAGE;
        uint32_t aS = aB[buf], bS = bB[buf];
#pragma unroll
        for (int s = 0; s < 4; s++) {
            uint32_t af[4][4], bf[4][2];
#pragma unroll
            for (int mt = 0; mt < 4; mt++)
                ldsm_x4(tile_addr(aS, wm * 64 + mt * 16 + a_row_l,
                                  s * 32 + a_bc_l), af[mt]);
#pragma unroll
            for (int nt = 0; nt < 4; nt++)
                ldsm_x2(tile_addr(bS, wn * 32 + nt * 8 + b_row_l,
                                  s * 32 + b_bc_l), bf[nt]);
#pragma unroll
            for (int mt = 0; mt < 4; mt++)
#pragma unroll
                for (int nt = 0; nt < 4; nt++)
                    mma_tf32(acc[mt][nt], af[mt], bf[nt][0], bf[nt][1]);
        }
    }

#pragma unroll
    for (int mt = 0; mt < 4; mt++) {
        int r0 = brow + wm * 64 + mt * 16 + (lane >> 2);
#pragma unroll
        for (int nt = 0; nt < 4; nt++) {
            int c = bcol + wn * 32 + nt * 8 + 2 * (lane & 3);
            float b0 = bias[c], b1 = bias[c + 1];
            float v00 = acc[mt][nt][0] + b0, v01 = acc[mt][nt][1] + b1;
            float v10 = acc[mt][nt][2] + b0, v11 = acc[mt][nt][3] + b1;
            if (do_round) {
                v00 = rnd_tf32(v00); v01 = rnd_tf32(v01);
                v10 = rnd_tf32(v10); v11 = rnd_tf32(v11);
            }
            *(float2*)(C + (size_t)r0 * N + c)       = make_float2(v00, v01);
            *(float2*)(C + (size_t)(r0 + 8) * N + c) = make_float2(v10, v11);
        }
    }
}

// ---------------------------------------------------------------------------
// Tensor-core flash attention (tf32 mma.sync, online softmax).
// SMALL-CTA VARIANT for 2 CTAs/SM: 128 threads (4 warps), 64 queries/CTA.
// Grid (S/64, B*H) = (32, 32). Warp w owns q-rows w*16..w*16+15.
// smem: Q/P 16KB | KT[2] 16KB ea | VT[2] 16KB ea = 80KB -> occ 2 (160/228KB).
// Per-thread register footprint unchanged vs R4 (no spill pressure at occ 2).
// ---------------------------------------------------------------------------
#define ATHR 128
#define ASMEM_BYTES (16384 + 2 * 16384 + 2 * 16384)

__global__ __launch_bounds__(ATHR, 2)
void attn_tc(const float* __restrict__ qkv, float* __restrict__ ctx) {
    extern __shared__ char smem[];
    uint32_t sbase = smem_u32(smem);
    uint32_t PS    = sbase;                                    // 16KB Q then P
    uint32_t KT[2] = { sbase + 16384, sbase + 16384 + 16384 };
    uint32_t VT[2] = { sbase + 49152, sbase + 49152 + 16384 };

    int tid  = threadIdx.x;
    int wid  = tid >> 5;            // 0..3
    int lane = tid & 31;
    int b    = blockIdx.y >> 4;
    int h    = blockIdx.y & 15;
    int q0   = blockIdx.x * 64;

    const float* base = qkv + (size_t)b * S_ * 3 * D_ + h * HD_;
    const float scale = 0.125f;

    int a_row_l = ((lane >> 3) & 1) * 8 + (lane & 7);
    int a_bc_l  = (lane >> 4) * 16;
    int b_row_l = lane & 7;
    int b_bc_l  = ((lane >> 3) & 1) * 16;

    // ---- Q -> smem (scaled): 64 rows x 16 float4 = 1024 chunks, 8/thread
    {
#pragma unroll
        for (int j = 0; j < 8; j++) {
            int idx = tid + j * ATHR;
            int r   = idx >> 4;
            int c16 = (idx & 15) * 16;
            float4 v = *(const float4*)(base + (size_t)(q0 + r) * (3 * D_) + (c16 >> 2));
            v.x *= scale; v.y *= scale; v.z *= scale; v.w *= scale;
            uint32_t ad = PS + swzA(r, c16);
            asm volatile("st.shared.v4.f32 [%0], {%1,%2,%3,%4};"
                         :: "r"(ad), "f"(v.x), "f"(v.y), "f"(v.z), "f"(v.w));
        }
    }
    __syncthreads();

    uint32_t qf[8][4];
#pragma unroll
    for (int ks = 0; ks < 8; ks++)
        ldsm_x4(PS + swzA(wid * 16 + a_row_l, ks * 32 + a_bc_l), qf[ks]);
    __syncthreads();   // Q consumed -> PS becomes P buffer

    float m0 = -1e30f, m1 = -1e30f, l0 = 0.f, l1 = 0.f;
    float o[8][4];
#pragma unroll
    for (int nt = 0; nt < 8; nt++)
#pragma unroll
        for (int k = 0; k < 4; k++) o[nt][k] = 0.f;

    // prologue fill: tile 0 -> buf 0 (1024 chunks each, 8/thread)
    {
        const float* kbase = base + D_;
        const float* vbase = base + 2 * D_;
#pragma unroll
        for (int j = 0; j < 8; j++) {
            int idx  = tid + j * ATHR;
            int krow = idx >> 4;
            int c16  = (idx & 15) * 16;
            cp16(KT[0] + swzA(krow, c16),
                 kbase + (size_t)krow * (3 * D_) + (c16 >> 2));
        }
        cp_commit();
#pragma unroll
        for (int j = 0; j < 8; j++) {
            int idx = tid + j * ATHR;
            int key = idx >> 4;
            int d4  = (idx & 15) * 4;
            float4 v = *(const float4*)(vbase + (size_t)key * (3 * D_) + d4);
            float vv[4] = {v.x, v.y, v.z, v.w};
#pragma unroll
            for (int e = 0; e < 4; e++) {
                uint32_t ad = VT[0] + swzA(d4 + e, key * 4);
                asm volatile("st.shared.f32 [%0], %1;" :: "r"(ad), "f"(vv[e]));
            }
        }
    }

    const int NT = S_ / 64;
    for (int kt = 0; kt < NT; kt++) {
        int buf = kt & 1;
        asm volatile("cp.async.wait_group 0;");
        __syncthreads();

        if (kt + 1 < NT) {
            int nxt = buf ^ 1;
            const float* kbase = base + (size_t)(kt + 1) * 64 * (3 * D_) + D_;
            const float* vbase = kbase + D_;
#pragma unroll
            for (int j = 0; j < 8; j++) {
                int idx  = tid + j * ATHR;
                int krow = idx >> 4;
                int c16  = (idx & 15) * 16;
                cp16(KT[nxt] + swzA(krow, c16),
                     kbase + (size_t)krow * (3 * D_) + (c16 >> 2));
            }
            cp_commit();
#pragma unroll
            for (int j = 0; j < 8; j++) {
                int idx = tid + j * ATHR;
                int key = idx >> 4;
                int d4  = (idx & 15) * 4;
                float4 v = *(const float4*)(vbase + (size_t)key * (3 * D_) + d4);
                float vv[4] = {v.x, v.y, v.z, v.w};
#pragma unroll
                for (int e = 0; e < 4; e++) {
                    uint32_t ad = VT[nxt] + swzA(d4 + e, key * 4);
                    asm volatile("st.shared.f32 [%0], %1;" :: "r"(ad), "f"(vv[e]));
                }
            }
        }

        // ---- QK^T
        float sc[8][4];
#pragma unroll
        for (int nt = 0; nt < 8; nt++)
#pragma unroll
            for (int k = 0; k < 4; k++) sc[nt][k] = 0.f;

#pragma unroll
        for (int ks = 0; ks < 8; ks++) {
            uint32_t bf[8][2];
#pragma unroll
            for (int nt = 0; nt < 8; nt++)
                ldsm_x2(KT[buf] + swzA(nt * 8 + b_row_l, ks * 32 + b_bc_l), bf[nt]);
#pragma unroll
            for (int nt = 0; nt < 8; nt++)
                mma_tf32(sc[nt], qf[ks], bf[nt][0], bf[nt][1]);
        }

        // ---- online softmax
        {
            float mt = -1e30f;
#pragma unroll
            for (int nt = 0; nt < 8; nt++)
                mt = fmaxf(mt, fmaxf(sc[nt][0], sc[nt][1]));
            mt = fmaxf(mt, __shfl_xor_sync(0xffffffffu, mt, 1));
            mt = fmaxf(mt, __shfl_xor_sync(0xffffffffu, mt, 2));
            float mn = fmaxf(m0, mt);
            float al = __expf(m0 - mn);
            m0 = mn;
            float rs = 0.f;
#pragma unroll
            for (int nt = 0; nt < 8; nt++) {
                sc[nt][0] = __expf(sc[nt][0] - mn);
                sc[nt][1] = __expf(sc[nt][1] - mn);
                rs += sc[nt][0] + sc[nt][1];
            }
            rs += __shfl_xor_sync(0xffffffffu, rs, 1);
            rs += __shfl_xor_sync(0xffffffffu, rs, 2);
            l0 = l0 * al + rs;
#pragma unroll
            for (int nt = 0; nt < 8; nt++) { o[nt][0] *= al; o[nt][1] *= al; }
        }
        {
            float mt = -1e30f;
#pragma unroll
            for (int nt = 0; nt < 8; nt++)
                mt = fmaxf(mt, fmaxf(sc[nt][2], sc[nt][3]));
            mt = fmaxf(mt, __shfl_xor_sync(0xffffffffu, mt, 1));
            mt = fmaxf(mt, __shfl_xor_sync(0xffffffffu, mt, 2));
            float mn = fmaxf(m1, mt);
            float al = __expf(m1 - mn);
            m1 = mn;
            float rs = 0.f;
#pragma unroll
            for (int nt = 0; nt < 8; nt++) {
                sc[nt][2] = __expf(sc[nt][2] - mn);
                sc[nt][3] = __expf(sc[nt][3] - mn);
                rs += sc[nt][2] + sc[nt][3];
            }
            rs += __shfl_xor_sync(0xffffffffu, rs, 1);
            rs += __shfl_xor_sync(0xffffffffu, rs, 2);
            l1 = l1 * al + rs;
#pragma unroll
            for (int nt = 0; nt < 8; nt++) { o[nt][2] *= al; o[nt][3] *= al; }
        }

        // ---- P (tf32-rounded) -> Ps (own warp's rows only)
        {
            int R0 = wid * 16 + (lane >> 2);
            int bcl = (lane & 3) * 8;
#pragma unroll
            for (int nt = 0; nt < 8; nt++) {
                uint32_t a0 = PS + swzA(R0,     nt * 32 + bcl);
                uint32_t a1 = PS + swzA(R0 + 8, nt * 32 + bcl);
                asm volatile("st.shared.v2.f32 [%0], {%1,%2};"
                             :: "r"(a0), "f"(rnd_tf32(sc[nt][0])), "f"(rnd_tf32(sc[nt][1])));
                asm volatile("st.shared.v2.f32 [%0], {%1,%2};"
                             :: "r"(a1), "f"(rnd_tf32(sc[nt][2])), "f"(rnd_tf32(sc[nt][3])));
            }
        }
        __syncwarp();

        // ---- O += P @ V
#pragma unroll
        for (int ks = 0; ks < 8; ks++) {
            uint32_t af[4];
            ldsm_x4(PS + swzA(wid * 16 + a_row_l, ks * 32 + a_bc_l), af);
            uint32_t bf[8][2];
#pragma unroll
            for (int nt = 0; nt < 8; nt++)
                ldsm_x2(VT[buf] + swzA(nt * 8 + b_row_l, ks * 32 + b_bc_l), bf[nt]);
#pragma unroll
            for (int nt = 0; nt < 8; nt++)
                mma_tf32(o[nt], af, bf[nt][0], bf[nt][1]);
        }
        __syncwarp();
    }

    // ---- epilogue
    {
        float i0 = 1.f / l0, i1 = 1.f / l1;
        int   r0 = q0 + wid * 16 + (lane >> 2);
        int   cc = h * HD_ + (lane & 3) * 2;
        float* c0 = ctx + ((size_t)b * S_ + r0) * D_ + cc;
        float* c1 = c0 + 8 * D_;
#pragma unroll
        for (int nt = 0; nt < 8; nt++) {
            *(float2*)(c0 + nt * 8) =
                make_float2(rnd_tf32(o[nt][0] * i0), rnd_tf32(o[nt][1] * i0));
            *(float2*)(c1 + nt * 8) =
                make_float2(rnd_tf32(o[nt][2] * i1), rnd_tf32(o[nt][3] * i1));
        }
    }
}

// ---------------------------------------------------------------------------
// Launch
// ---------------------------------------------------------------------------
extern "C" void kernel_launch(void* const* d_in, const int* in_sizes, int n_in,
                              void* d_out, int out_size) {
    const float* x    = (const float*)d_in[0];
    const float* Wqkv = (const float*)d_in[1];
    const float* bqkv = (const float*)d_in[2];
    const float* Wout = (const float*)d_in[3];
    const float* bout = (const float*)d_in[4];
    float* out = (float*)d_out;

    void *qkv_p, *ctx_p, *xt_p, *wq_p, *wo_p;
    cudaGetSymbolAddress(&qkv_p, g_qkv);
    cudaGetSymbolAddress(&ctx_p, g_ctx);
    cudaGetSymbolAddress(&xt_p,  g_xt);
    cudaGetSymbolAddress(&wq_p,  g_wqkv_t);
    cudaGetSymbolAddress(&wo_p,  g_wout_t);
    float* qkv   = (float*)qkv_p;
    float* ctx   = (float*)ctx_p;
    float* xt    = (float*)xt_p;
    float* wqkvt = (float*)wq_p;
    float* woutt = (float*)wo_p;

    cudaFuncSetAttribute(gemm_tc, cudaFuncAttributeMaxDynamicSharedMemorySize,
                         GSMEM_BYTES);
    cudaFuncSetAttribute(attn_tc, cudaFuncAttributeMaxDynamicSharedMemorySize,
                         ASMEM_BYTES);

    // Pre-pass
    int n4 = MTOT * D_ / 4;
    round_tf32_vec4<<<(n4 + 255) / 256, 256>>>(x, xt, n4);
    transpose_round<<<dim3(3 * D_ / 32, D_ / 32), dim3(32, 8)>>>(Wqkv, wqkvt, D_, 3 * D_);
    transpose_round<<<dim3(D_ / 32, D_ / 32), dim3(32, 8)>>>(Wout, woutt, D_, D_);

    // 1) QKV projection (round outputs -> attention consumes tf32)
    gemm_tc<<<dim3(3 * D_ / 128, MTOT / 128), 256, GSMEM_BYTES>>>(
        xt, wqkvt, bqkv, qkv, 3 * D_, 1);

    // 2) Attention (tensor-core flash, 2 CTAs/SM)
    attn_tc<<<dim3(S_ / 64, B_ * H_), ATHR, ASMEM_BYTES>>>(qkv, ctx);

    // 3) Output projection (no rounding — final output)
    gemm_tc<<<dim3(D_ / 128, MTOT / 128), 256, GSMEM_BYTES>>>(
        ctx, woutt, bout, out, D_, 0);
}

// round 8
// speedup vs baseline: 1.1053x; 1.1053x over previous
#include <cuda_runtime.h>
#include <stdint.h>
#include <math.h>

#define B_  2
#define S_  2048
#define D_  1024
#define H_  16
#define HD_ 64
#define MTOT (B_ * S_)           // 4096

// ---------------------------------------------------------------------------
// Scratch (__device__ globals: allocation-free rule)
// ---------------------------------------------------------------------------
__device__ float g_qkv[(size_t)B_ * S_ * 3 * D_];   // [B,S,3D] (tf32-rounded)
__device__ float g_ctx[(size_t)B_ * S_ * D_];       // [B,S,D]  (tf32-rounded)
__device__ float g_xt[(size_t)MTOT * D_];           // x, tf32-rounded
__device__ float g_wqkv_t[(size_t)3 * D_ * D_];     // W_qkv^T [3D, D]
__device__ float g_wout_t[(size_t)D_ * D_];         // W_out^T [D, D]

// ---------------------------------------------------------------------------
// Helpers (baseline-PTX only: cp.async, ldmatrix, mma.sync)
// ---------------------------------------------------------------------------
__device__ __forceinline__ uint32_t smem_u32(const void* p) {
    uint32_t a;
    asm("{ .reg .u64 t; cvta.to.shared.u64 t, %1; cvt.u32.u64 %0, t; }"
        : "=r"(a) : "l"(p));
    return a;
}
__device__ __forceinline__ float rnd_tf32(float x) {
    uint32_t u;
    asm("cvt.rna.tf32.f32 %0, %1;" : "=r"(u) : "f"(x));
    return __uint_as_float(u);
}
__device__ __forceinline__ void cp16(uint32_t dst, const void* src) {
    asm volatile("cp.async.cg.shared.global [%0], [%1], 16;"
                 :: "r"(dst), "l"(src));
}
__device__ __forceinline__ void cp_commit() {
    asm volatile("cp.async.commit_group;");
}
__device__ __forceinline__ void ldsm_x4(uint32_t addr, uint32_t* r) {
    asm volatile("ldmatrix.sync.aligned.m8n8.x4.shared.b16 {%0,%1,%2,%3}, [%4];"
                 : "=r"(r[0]), "=r"(r[1]), "=r"(r[2]), "=r"(r[3]) : "r"(addr));
}
__device__ __forceinline__ void ldsm_x2(uint32_t addr, uint32_t* r) {
    asm volatile("ldmatrix.sync.aligned.m8n8.x2.shared.b16 {%0,%1}, [%2];"
                 : "=r"(r[0]), "=r"(r[1]) : "r"(addr));
}
__device__ __forceinline__ void mma_tf32(float* c, const uint32_t* a,
                                         uint32_t b0, uint32_t b1) {
    asm volatile(
        "mma.sync.aligned.m16n8k8.row.col.f32.tf32.tf32.f32 "
        "{%0,%1,%2,%3}, {%4,%5,%6,%7}, {%8,%9}, {%0,%1,%2,%3};"
        : "+f"(c[0]), "+f"(c[1]), "+f"(c[2]), "+f"(c[3])
        : "r"(a[0]), "r"(a[1]), "r"(a[2]), "r"(a[3]), "r"(b0), "r"(b1));
}

// GEMM tile addressing: 128B rows (32 floats)
__device__ __forceinline__ uint32_t tile_addr(uint32_t base, int row, int bc) {
    return base + (uint32_t)(row * 128) + (uint32_t)(bc ^ ((row & 7) << 4));
}
// Attention tile addressing: 256B rows (64 floats), 2-level XOR swizzle
__device__ __forceinline__ uint32_t swzA(int row, int bc) {
    int nib = ((row & 7) ^ ((row >> 3) & 7)) << 4;
    return (uint32_t)(row * 256 + (bc ^ nib));
}

// ---------------------------------------------------------------------------
// Pre-pass kernels
// ---------------------------------------------------------------------------
__global__ void round_tf32_vec4(const float* __restrict__ in,
                                float* __restrict__ out, int n4) {
    int i = blockIdx.x * blockDim.x + threadIdx.x;
    if (i < n4) {
        float4 v = ((const float4*)in)[i];
        v.x = rnd_tf32(v.x); v.y = rnd_tf32(v.y);
        v.z = rnd_tf32(v.z); v.w = rnd_tf32(v.w);
        ((float4*)out)[i] = v;
    }
}

__global__ void transpose_round(const float* __restrict__ W,
                                float* __restrict__ Wt, int K, int N) {
    __shared__ float t[32][33];
    int bx = blockIdx.x * 32;
    int by = blockIdx.y * 32;
    int x = threadIdx.x, y = threadIdx.y;   // block (32, 8)
#pragma unroll
    for (int j = 0; j < 32; j += 8)
        t[y + j][x] = W[(size_t)(by + y + j) * N + bx + x];
    __syncthreads();
#pragma unroll
    for (int j = 0; j < 32; j += 8)
        Wt[(size_t)(bx + y + j) * K + by + x] = rnd_tf32(t[x][y + j]);
}

// ---------------------------------------------------------------------------
// Tensor-core tf32 GEMM + bias (mma.sync).
// 3-stage cp.async pipeline, one __syncthreads per K-iter.
// ---------------------------------------------------------------------------
#define GK    1024
#define BK    32
#define NKIT  (GK / BK)
#define STAGE_BYTES 32768
#define NSTAGE 3
#define GSMEM_BYTES (NSTAGE * STAGE_BYTES)

__global__ __launch_bounds__(256, 2)
void gemm_tc(const float* __restrict__ A, const float* __restrict__ Bt,
             const float* __restrict__ bias, float* __restrict__ C, int N,
             int do_round) {
    extern __shared__ char smem[];
    uint32_t sbase = smem_u32(smem);

    int tid  = threadIdx.x;
    int wid  = tid >> 5;
    int lane = tid & 31;
    int wm   = wid >> 2;
    int wn   = wid & 3;
    int brow = blockIdx.y * 128;
    int bcol = blockIdx.x * 128;

    uint32_t aB[NSTAGE], bB[NSTAGE];
#pragma unroll
    for (int s = 0; s < NSTAGE; s++) {
        aB[s] = sbase + s * STAGE_BYTES;
        bB[s] = aB[s] + 16384;
    }

    const float* Agp = A  + (size_t)brow * GK;
    const float* Bgp = Bt + (size_t)bcol * GK;

    int cr = tid >> 3, cc16 = (tid & 7) * 16;

    int a_row_l = ((lane >> 3) & 1) * 8 + (lane & 7);
    int a_bc_l  = (lane >> 4) * 16;
    int b_row_l = lane & 7;
    int b_bc_l  = ((lane >> 3) & 1) * 16;

    float acc[4][4][4];
#pragma unroll
    for (int i = 0; i < 4; i++)
#pragma unroll
        for (int j = 0; j < 4; j++)
#pragma unroll
            for (int k = 0; k < 4; k++) acc[i][j][k] = 0.f;

#pragma unroll
    for (int s = 0; s < 2; s++) {
        int k0 = s * BK;
#pragma unroll
        for (int j = 0; j < 4; j++) {
            int row = cr + j * 32;
            uint32_t off = tile_addr(0, row, cc16);
            cp16(aB[s] + off, Agp + (size_t)row * GK + k0 + (cc16 >> 2));
            cp16(bB[s] + off, Bgp + (size_t)row * GK + k0 + (cc16 >> 2));
        }
        cp_commit();
    }

    for (int it = 0; it < NKIT; it++) {
        if (it + 1 < NKIT) {
            asm volatile("cp.async.wait_group 1;");
        } else {
            asm volatile("cp.async.wait_group 0;");
        }
        __syncthreads();

        if (it + 2 < NKIT) {
            int s  = (it + 2) % NSTAGE;
            int k0 = (it + 2) * BK;
#pragma unroll
            for (int j = 0; j < 4; j++) {
                int row = cr + j * 32;
                uint32_t off = tile_addr(0, row, cc16);
                cp16(aB[s] + off, Agp + (size_t)row * GK + k0 + (cc16 >> 2));
                cp16(bB[s] + off, Bgp + (size_t)row * GK + k0 + (cc16 >> 2));
            }
            cp_commit();
        }

        int buf = it % NSTAGE;
        uint32_t aS = aB[buf], bS = bB[buf];
#pragma unroll
        for (int s = 0; s < 4; s++) {
            uint32_t af[4][4], bf[4][2];
#pragma unroll
            for (int mt = 0; mt < 4; mt++)
                ldsm_x4(tile_addr(aS, wm * 64 + mt * 16 + a_row_l,
                                  s * 32 + a_bc_l), af[mt]);
#pragma unroll
            for (int nt = 0; nt < 4; nt++)
                ldsm_x2(tile_addr(bS, wn * 32 + nt * 8 + b_row_l,
                                  s * 32 + b_bc_l), bf[nt]);
#pragma unroll
            for (int mt = 0; mt < 4; mt++)
#pragma unroll
                for (int nt = 0; nt < 4; nt++)
                    mma_tf32(acc[mt][nt], af[mt], bf[nt][0], bf[nt][1]);
        }
    }

#pragma unroll
    for (int mt = 0; mt < 4; mt++) {
        int r0 = brow + wm * 64 + mt * 16 + (lane >> 2);
#pragma unroll
        for (int nt = 0; nt < 4; nt++) {
            int c = bcol + wn * 32 + nt * 8 + 2 * (lane & 3);
            float b0 = bias[c], b1 = bias[c + 1];
            float v00 = acc[mt][nt][0] + b0, v01 = acc[mt][nt][1] + b1;
            float v10 = acc[mt][nt][2] + b0, v11 = acc[mt][nt][3] + b1;
            if (do_round) {
                v00 = rnd_tf32(v00); v01 = rnd_tf32(v01);
                v10 = rnd_tf32(v10); v11 = rnd_tf32(v11);
            }
            *(float2*)(C + (size_t)r0 * N + c)       = make_float2(v00, v01);
            *(float2*)(C + (size_t)(r0 + 8) * N + c) = make_float2(v10, v11);
        }
    }
}

// ---------------------------------------------------------------------------
// Tensor-core flash attention (tf32 mma.sync, online softmax).
// R4 config: grid (S/128, B*H), 256 threads (8 warps), occ 1.
// CHANGE vs R4: V prefetch split — LDG issued right after the barrier
// (latency hidden under QK^T + softmax), transposed STS deferred to after
// the PV mma. The next-iteration __syncthreads orders the STS for consumers.
// ---------------------------------------------------------------------------
#define ASMEM_BYTES (32768 + 2 * 16384 + 2 * 16384)

__global__ __launch_bounds__(256, 1)
void attn_tc(const float* __restrict__ qkv, float* __restrict__ ctx) {
    extern __shared__ char smem[];
    uint32_t sbase = smem_u32(smem);
    uint32_t PS    = sbase;
    uint32_t KT[2] = { sbase + 32768, sbase + 32768 + 16384 };
    uint32_t VT[2] = { sbase + 65536, sbase + 65536 + 16384 };

    int tid  = threadIdx.x;
    int wid  = tid >> 5;
    int lane = tid & 31;
    int b    = blockIdx.y >> 4;
    int h    = blockIdx.y & 15;
    int q0   = blockIdx.x * 128;

    const float* base = qkv + (size_t)b * S_ * 3 * D_ + h * HD_;
    const float scale = 0.125f;

    int a_row_l = ((lane >> 3) & 1) * 8 + (lane & 7);
    int a_bc_l  = (lane >> 4) * 16;
    int b_row_l = lane & 7;
    int b_bc_l  = ((lane >> 3) & 1) * 16;

    // V prefetch static per-thread mapping (4 chunks/thread/tile)
    int v_key[4], v_d4[4];
#pragma unroll
    for (int j = 0; j < 4; j++) {
        int idx  = tid + j * 256;
        v_key[j] = idx >> 4;
        v_d4[j]  = (idx & 15) * 4;
    }

    // ---- Q -> smem (scaled), then cache fragments in registers
    {
        for (int j = 0; j < 8; j++) {
            int idx = tid + j * 256;
            int r   = idx >> 4;
            int c16 = (idx & 15) * 16;
            float4 v = *(const float4*)(base + (size_t)(q0 + r) * (3 * D_) + (c16 >> 2));
            v.x *= scale; v.y *= scale; v.z *= scale; v.w *= scale;
            uint32_t ad = PS + swzA(r, c16);
            asm volatile("st.shared.v4.f32 [%0], {%1,%2,%3,%4};"
                         :: "r"(ad), "f"(v.x), "f"(v.y), "f"(v.z), "f"(v.w));
        }
    }
    __syncthreads();

    uint32_t qf[8][4];
#pragma unroll
    for (int ks = 0; ks < 8; ks++)
        ldsm_x4(PS + swzA(wid * 16 + a_row_l, ks * 32 + a_bc_l), qf[ks]);
    __syncthreads();   // Qs fully consumed -> becomes Ps

    float m0 = -1e30f, m1 = -1e30f, l0 = 0.f, l1 = 0.f;
    float o[8][4];
#pragma unroll
    for (int nt = 0; nt < 8; nt++)
#pragma unroll
        for (int k = 0; k < 4; k++) o[nt][k] = 0.f;

    // prologue fill: tile 0 -> buf 0 (K cp.async; V LDG+STS directly)
    {
        const float* kbase = base + D_;
        const float* vbase = base + 2 * D_;
#pragma unroll
        for (int j = 0; j < 4; j++) {
            int idx  = tid + j * 256;
            int krow = idx >> 4;
            int c16  = (idx & 15) * 16;
            cp16(KT[0] + swzA(krow, c16),
                 kbase + (size_t)krow * (3 * D_) + (c16 >> 2));
        }
        cp_commit();
#pragma unroll
        for (int j = 0; j < 4; j++) {
            float4 v = *(const float4*)(vbase + (size_t)v_key[j] * (3 * D_) + v_d4[j]);
            float vv[4] = {v.x, v.y, v.z, v.w};
#pragma unroll
            for (int e = 0; e < 4; e++) {
                uint32_t ad = VT[0] + swzA(v_d4[j] + e, v_key[j] * 4);
                asm volatile("st.shared.f32 [%0], %1;" :: "r"(ad), "f"(vv[e]));
            }
        }
    }

    const int NT = S_ / 64;
    for (int kt = 0; kt < NT; kt++) {
        int buf = kt & 1;
        asm volatile("cp.async.wait_group 0;");
        __syncthreads();

        // ---- prefetch next tile: K via cp.async; V LDG only (STS deferred)
        float4 vreg[4];
        if (kt + 1 < NT) {
            int nxt = buf ^ 1;
            const float* kbase = base + (size_t)(kt + 1) * 64 * (3 * D_) + D_;
            const float* vbase = kbase + D_;
#pragma unroll
            for (int j = 0; j < 4; j++) {
                int idx  = tid + j * 256;
                int krow = idx >> 4;
                int c16  = (idx & 15) * 16;
                cp16(KT[nxt] + swzA(krow, c16),
                     kbase + (size_t)krow * (3 * D_) + (c16 >> 2));
            }
            cp_commit();
#pragma unroll
            for (int j = 0; j < 4; j++)
                vreg[j] = *(const float4*)(vbase + (size_t)v_key[j] * (3 * D_) + v_d4[j]);
            (void)nxt;
        }

        // ---- QK^T
        float sc[8][4];
#pragma unroll
        for (int nt = 0; nt < 8; nt++)
#pragma unroll
            for (int k = 0; k < 4; k++) sc[nt][k] = 0.f;

#pragma unroll
        for (int ks = 0; ks < 8; ks++) {
            uint32_t bf[8][2];
#pragma unroll
            for (int nt = 0; nt < 8; nt++)
                ldsm_x2(KT[buf] + swzA(nt * 8 + b_row_l, ks * 32 + b_bc_l), bf[nt]);
#pragma unroll
            for (int nt = 0; nt < 8; nt++)
                mma_tf32(sc[nt], qf[ks], bf[nt][0], bf[nt][1]);
        }

        // ---- online softmax
        {
            float mt = -1e30f;
#pragma unroll
            for (int nt = 0; nt < 8; nt++)
                mt = fmaxf(mt, fmaxf(sc[nt][0], sc[nt][1]));
            mt = fmaxf(mt, __shfl_xor_sync(0xffffffffu, mt, 1));
            mt = fmaxf(mt, __shfl_xor_sync(0xffffffffu, mt, 2));
            float mn = fmaxf(m0, mt);
            float al = __expf(m0 - mn);
            m0 = mn;
            float rs = 0.f;
#pragma unroll
            for (int nt = 0; nt < 8; nt++) {
                sc[nt][0] = __expf(sc[nt][0] - mn);
                sc[nt][1] = __expf(sc[nt][1] - mn);
                rs += sc[nt][0] + sc[nt][1];
            }
            rs += __shfl_xor_sync(0xffffffffu, rs, 1);
            rs += __shfl_xor_sync(0xffffffffu, rs, 2);
            l0 = l0 * al + rs;
#pragma unroll
            for (int nt = 0; nt < 8; nt++) { o[nt][0] *= al; o[nt][1] *= al; }
        }
        {
            float mt = -1e30f;
#pragma unroll
            for (int nt = 0; nt < 8; nt++)
                mt = fmaxf(mt, fmaxf(sc[nt][2], sc[nt][3]));
            mt = fmaxf(mt, __shfl_xor_sync(0xffffffffu, mt, 1));
            mt = fmaxf(mt, __shfl_xor_sync(0xffffffffu, mt, 2));
            float mn = fmaxf(m1, mt);
            float al = __expf(m1 - mn);
            m1 = mn;
            float rs = 0.f;
#pragma unroll
            for (int nt = 0; nt < 8; nt++) {
                sc[nt][2] = __expf(sc[nt][2] - mn);
                sc[nt][3] = __expf(sc[nt][3] - mn);
                rs += sc[nt][2] + sc[nt][3];
            }
            rs += __shfl_xor_sync(0xffffffffu, rs, 1);
            rs += __shfl_xor_sync(0xffffffffu, rs, 2);
            l1 = l1 * al + rs;
#pragma unroll
            for (int nt = 0; nt < 8; nt++) { o[nt][2] *= al; o[nt][3] *= al; }
        }

        // ---- P (tf32-rounded) -> Ps (own warp's rows only)
        {
            int R0 = wid * 16 + (lane >> 2);
            int bcl = (lane & 3) * 8;
#pragma unroll
            for (int nt = 0; nt < 8; nt++) {
                uint32_t a0 = PS + swzA(R0,     nt * 32 + bcl);
                uint32_t a1 = PS + swzA(R0 + 8, nt * 32 + bcl);
                asm volatile("st.shared.v2.f32 [%0], {%1,%2};"
                             :: "r"(a0), "f"(rnd_tf32(sc[nt][0])), "f"(rnd_tf32(sc[nt][1])));
                asm volatile("st.shared.v2.f32 [%0], {%1,%2};"
                             :: "r"(a1), "f"(rnd_tf32(sc[nt][2])), "f"(rnd_tf32(sc[nt][3])));
            }
        }
        __syncwarp();

        // ---- O += P @ V
#pragma unroll
        for (int ks = 0; ks < 8; ks++) {
            uint32_t af[4];
            ldsm_x4(PS + swzA(wid * 16 + a_row_l, ks * 32 + a_bc_l), af);
            uint32_t bf[8][2];
#pragma unroll
            for (int nt = 0; nt < 8; nt++)
                ldsm_x2(VT[buf] + swzA(nt * 8 + b_row_l, ks * 32 + b_bc_l), bf[nt]);
#pragma unroll
            for (int nt = 0; nt < 8; nt++)
                mma_tf32(o[nt], af, bf[nt][0], bf[nt][1]);
        }
        __syncwarp();

        // ---- deferred V transpose STS for next tile (ordered by next barrier)
        if (kt + 1 < NT) {
            int nxt = buf ^ 1;
#pragma unroll
            for (int j = 0; j < 4; j++) {
                float vv[4] = {vreg[j].x, vreg[j].y, vreg[j].z, vreg[j].w};
#pragma unroll
                for (int e = 0; e < 4; e++) {
                    uint32_t ad = VT[nxt] + swzA(v_d4[j] + e, v_key[j] * 4);
                    asm volatile("st.shared.f32 [%0], %1;" :: "r"(ad), "f"(vv[e]));
                }
            }
        }
    }

    // ---- epilogue
    {
        float i0 = 1.f / l0, i1 = 1.f / l1;
        int   r0 = q0 + wid * 16 + (lane >> 2);
        int   cc = h * HD_ + (lane & 3) * 2;
        float* c0 = ctx + ((size_t)b * S_ + r0) * D_ + cc;
        float* c1 = c0 + 8 * D_;
#pragma unroll
        for (int nt = 0; nt < 8; nt++) {
            *(float2*)(c0 + nt * 8) =
                make_float2(rnd_tf32(o[nt][0] * i0), rnd_tf32(o[nt][1] * i0));
            *(float2*)(c1 + nt * 8) =
                make_float2(rnd_tf32(o[nt][2] * i1), rnd_tf32(o[nt][3] * i1));
        }
    }
}

// ---------------------------------------------------------------------------
// Launch
// ---------------------------------------------------------------------------
extern "C" void kernel_launch(void* const* d_in, const int* in_sizes, int n_in,
                              void* d_out, int out_size) {
    const float* x    = (const float*)d_in[0];
    const float* Wqkv = (const float*)d_in[1];
    const float* bqkv = (const float*)d_in[2];
    const float* Wout = (const float*)d_in[3];
    const float* bout = (const float*)d_in[4];
    float* out = (float*)d_out;

    void *qkv_p, *ctx_p, *xt_p, *wq_p, *wo_p;
    cudaGetSymbolAddress(&qkv_p, g_qkv);
    cudaGetSymbolAddress(&ctx_p, g_ctx);
    cudaGetSymbolAddress(&xt_p,  g_xt);
    cudaGetSymbolAddress(&wq_p,  g_wqkv_t);
    cudaGetSymbolAddress(&wo_p,  g_wout_t);
    float* qkv   = (float*)qkv_p;
    float* ctx   = (float*)ctx_p;
    float* xt    = (float*)xt_p;
    float* wqkvt = (float*)wq_p;
    float* woutt = (float*)wo_p;

    cudaFuncSetAttribute(gemm_tc, cudaFuncAttributeMaxDynamicSharedMemorySize,
                         GSMEM_BYTES);
    cudaFuncSetAttribute(attn_tc, cudaFuncAttributeMaxDynamicSharedMemorySize,
                         ASMEM_BYTES);

    // Pre-pass
    int n4 = MTOT * D_ / 4;
    round_tf32_vec4<<<(n4 + 255) / 256, 256>>>(x, xt, n4);
    transpose_round<<<dim3(3 * D_ / 32, D_ / 32), dim3(32, 8)>>>(Wqkv, wqkvt, D_, 3 * D_);
    transpose_round<<<dim3(D_ / 32, D_ / 32), dim3(32, 8)>>>(Wout, woutt, D_, D_);

    // 1) QKV projection (round outputs -> attention consumes tf32)
    gemm_tc<<<dim3(3 * D_ / 128, MTOT / 128), 256, GSMEM_BYTES>>>(
        xt, wqkvt, bqkv, qkv, 3 * D_, 1);

    // 2) Attention (tensor-core flash)
    attn_tc<<<dim3(S_ / 128, B_ * H_), 256, ASMEM_BYTES>>>(qkv, ctx);

    // 3) Output projection (no rounding — final output)
    gemm_tc<<<dim3(D_ / 128, MTOT / 128), 256, GSMEM_BYTES>>>(
        ctx, woutt, bout, out, D_, 0);
}